// round 1
// baseline (speedup 1.0000x reference)
#include <cuda_runtime.h>
#include <math.h>

#define BB 8
#define AA 49104
#define MM 50
#define KK 80

// scratch accumulators (no allocations allowed)
__device__ float g_cls_raw[BB];
__device__ float g_reg_raw[BB];
__device__ int   g_numpos[BB];
__device__ int   g_nvalid[BB];

__global__ void init_kernel(const float* __restrict__ boxes) {
    int b = threadIdx.x;
    if (b < BB) {
        g_cls_raw[b] = 0.0f;
        g_reg_raw[b] = 0.0f;
        g_numpos[b] = 0;
        int nv = 0;
        #pragma unroll
        for (int j = 0; j < MM; ++j)
            if (boxes[((size_t)b * MM + j) * 4] != -1.0f) nv++;
        g_nvalid[b] = nv;
    }
}

__device__ __forceinline__ float smooth_l1(float d) {
    const float BETA = 1.0f / 9.0f;
    float ad = fabsf(d);
    // 0.5*ad*ad/BETA = 4.5*ad*ad ; ad - 0.5*BETA
    return (ad <= BETA) ? (0.5f * ad * ad / BETA) : (ad - 0.5f * BETA);
}

__global__ __launch_bounds__(256) void retina_main_kernel(
    const float* __restrict__ logits,   // (B,A,K)
    const float* __restrict__ regp,     // (B,A,4)
    const float* __restrict__ anchors,  // (A,4)
    const float* __restrict__ boxes,    // (B,M,4)
    const int*   __restrict__ cls)      // (B,M)
{
    const int b = blockIdx.y;
    const int a = blockIdx.x * blockDim.x + threadIdx.x;

    __shared__ float4 sbox[MM];   // x1,y1,x2,y2
    __shared__ float4 saux[MM];   // t4=(2/7)*area_b, t5=(1/3)*area_b, area_b, cls-as-bits
    __shared__ int snv;

    if (threadIdx.x < MM) {
        int j = threadIdx.x;
        float4 bx = ((const float4*)boxes)[b * MM + j];
        float sb = (bx.z - bx.x) * (bx.w - bx.y);
        sbox[j] = bx;
        float4 au;
        au.x = sb * (2.0f / 7.0f);
        au.y = sb * (1.0f / 3.0f);
        au.z = sb;
        au.w = __int_as_float(cls[b * MM + j]);
        saux[j] = au;
    }
    if (threadIdx.x == 0) snv = g_nvalid[b];
    __syncthreads();
    const int nv = snv;

    float s = 0.0f;  // classification partial sum, in units of p^2*log2(...)

    if (a < AA) {
        float4 an = ((const float4*)anchors)[a];
        const float ax1 = an.x, ay1 = an.y, ax2 = an.z, ay2 = an.w;
        const float aw = ax2 - ax1, ah = ay2 - ay1;
        const float sa = aw * ah;

        // ---- assignment screen: division-free threshold tests ----
        // iou >= t  <=>  inter >= t/(1+t) * (sa + sb)
        float m4 = -1e30f, m5 = -1e30f;
        #pragma unroll 2
        for (int j = 0; j < nv; ++j) {
            float4 bx = sbox[j];
            float4 au = saux[j];
            float iw = fmaxf(fminf(ax2, bx.z) - fmaxf(ax1, bx.x), 0.0f);
            float ih = fmaxf(fminf(ay2, bx.w) - fmaxf(ay1, bx.y), 0.0f);
            float inter = iw * ih;
            m4 = fmaxf(m4, inter - au.x);
            m5 = fmaxf(m5, inter - au.y);
        }
        const bool pos = (m5 >= sa * (1.0f / 3.0f));
        const bool neg = (m4 <  sa * (2.0f / 7.0f));
        const bool ignore = (!pos) && (!neg);

        const float* row = logits + ((size_t)b * AA + a) * KK;

        if (!ignore) {
            // bulk focal: all-targets-zero term  f(p) = p^2 * log2(1-p)
            const float4* row4 = (const float4*)row;
            #pragma unroll 4
            for (int i = 0; i < KK / 4; ++i) {
                float4 p4 = row4[i];
                float p0 = fminf(fmaxf(p4.x, 1e-4f), 1.0f - 1e-4f);
                float p1 = fminf(fmaxf(p4.y, 1e-4f), 1.0f - 1e-4f);
                float p2 = fminf(fmaxf(p4.z, 1e-4f), 1.0f - 1e-4f);
                float p3 = fminf(fmaxf(p4.w, 1e-4f), 1.0f - 1e-4f);
                s += p0 * p0 * __log2f(1.0f - p0);
                s += p1 * p1 * __log2f(1.0f - p1);
                s += p2 * p2 * __log2f(1.0f - p2);
                s += p3 * p3 * __log2f(1.0f - p3);
            }
        }

        if (pos) {
            // ---- argmax over iou, division-free cross-multiplication ----
            // track (best_inter, best_ua); iou_j > best  <=>  inter_j*bu > bi*ua_j
            float bi = -1.0f, bu = 1.0f;
            int bj = 0;
            for (int j = 0; j < nv; ++j) {
                float4 bx = sbox[j];
                float iw = fmaxf(fminf(ax2, bx.z) - fmaxf(ax1, bx.x), 0.0f);
                float ih = fmaxf(fminf(ay2, bx.w) - fmaxf(ay1, bx.y), 0.0f);
                float inter = iw * ih;
                float ua = fmaxf(sa + saux[j].z - inter, 1e-8f);
                if (inter * bu > bi * ua) { bi = inter; bu = ua; bj = j; }
            }
            atomicAdd(&g_numpos[b], 1);

            // focal correction on the positive class:
            // replace f(p_c) with (1/3)*(1-p)^2*log2(p)  (scale folded: 0.25 = 0.75/3)
            int c = __float_as_int(saux[bj].w) - 1;
            float praw = row[c];
            float p = fminf(fmaxf(praw, 1e-4f), 1.0f - 1e-4f);
            float q = 1.0f - p;
            s += (1.0f / 3.0f) * q * q * __log2f(p) - p * p * __log2f(q);

            // regression smooth-L1 for this anchor
            float4 gb = sbox[bj];
            float acx = ax1 + 0.5f * aw;
            float acy = ay1 + 0.5f * ah;
            float gw0 = gb.z - gb.x, gh0 = gb.w - gb.y;
            float gcx = gb.x + 0.5f * gw0;
            float gcy = gb.y + 0.5f * gh0;
            float gw = fmaxf(gw0, 1.0f), gh = fmaxf(gh0, 1.0f);
            float4 rp = ((const float4*)regp)[b * AA + a];
            float t0 = ((gcx - acx) / aw) / 0.1f;
            float t1 = ((gcy - acy) / ah) / 0.1f;
            float t2 = logf(gw / aw) / 0.2f;
            float t3 = logf(gh / ah) / 0.2f;
            float rsum = smooth_l1(t0 - rp.x) + smooth_l1(t1 - rp.y)
                       + smooth_l1(t2 - rp.z) + smooth_l1(t3 - rp.w);
            atomicAdd(&g_reg_raw[b], rsum);
        }
    }

    // ---- block reduction of the cls partial, one atomic per block ----
    #pragma unroll
    for (int o = 16; o > 0; o >>= 1)
        s += __shfl_down_sync(0xffffffffu, s, o);

    __shared__ float wsum[8];
    int lane = threadIdx.x & 31;
    int wid = threadIdx.x >> 5;
    if (lane == 0) wsum[wid] = s;
    __syncthreads();
    if (threadIdx.x == 0) {
        float t = 0.0f;
        #pragma unroll
        for (int i = 0; i < 8; ++i) t += wsum[i];
        atomicAdd(&g_cls_raw[b], t);
    }
}

__global__ void final_kernel(float* __restrict__ out) {
    if (threadIdx.x == 0 && blockIdx.x == 0) {
        float cm = 0.0f, rm = 0.0f;
        #pragma unroll
        for (int b = 0; b < BB; ++b) {
            float np = fmaxf((float)g_numpos[b], 1.0f);
            // s accumulated p^2*lg2(1-p) etc; actual loss = -0.75*ln2 * s
            cm += (-0.75f * 0.69314718055994531f) * g_cls_raw[b] / np;
            rm += g_reg_raw[b] / (4.0f * np);
        }
        cm *= (1.0f / (float)BB);
        rm *= (1.0f / (float)BB);
        out[0] = cm;
        out[1] = rm;
        out[2] = cm + rm;
    }
}

extern "C" void kernel_launch(void* const* d_in, const int* in_sizes, int n_in,
                              void* d_out, int out_size) {
    const float* logits  = (const float*)d_in[0];
    const float* regp    = (const float*)d_in[1];
    const float* anchors = (const float*)d_in[2];
    const float* boxes   = (const float*)d_in[3];
    const int*   cls     = (const int*)d_in[4];
    float* out = (float*)d_out;

    init_kernel<<<1, 32>>>(boxes);
    dim3 grid((AA + 255) / 256, BB);
    retina_main_kernel<<<grid, 256>>>(logits, regp, anchors, boxes, cls);
    final_kernel<<<1, 32>>>(out);
}

// round 2
// speedup vs baseline: 1.0471x; 1.0471x over previous
#include <cuda_runtime.h>
#include <math.h>

#define BB 8
#define AA 49104
#define MM 50
#define KK 80
#define TPB 256
#define ANCH_PER_BLK 256
#define NBLKX ((AA + ANCH_PER_BLK - 1) / ANCH_PER_BLK)   // 192
#define NBLKS (NBLKX * BB)                               // 1536

// zero-initialized at module load; finalizer re-zeros after each consume,
// so every graph replay starts clean.
__device__ float g_cls_raw[BB];
__device__ float g_reg_raw[BB];
__device__ int   g_numpos[BB];
__device__ unsigned int g_done;

__device__ __forceinline__ float smooth_l1(float d) {
    const float BETA = 1.0f / 9.0f;
    float ad = fabsf(d);
    return (ad <= BETA) ? (4.5f * ad * ad) : (ad - 0.5f * BETA);
}

__global__ __launch_bounds__(TPB) void retina_fused_kernel(
    const float* __restrict__ logits,   // (B,A,K)
    const float* __restrict__ regp,     // (B,A,4)
    const float* __restrict__ anchors,  // (A,4)
    const float* __restrict__ boxes,    // (B,M,4)
    const int*   __restrict__ cls,      // (B,M)
    float* __restrict__ out)
{
    const int b = blockIdx.y;
    const int tid = threadIdx.x;
    const int aStart = blockIdx.x * ANCH_PER_BLK;
    const int a = aStart + tid;
    const int aCnt = min(ANCH_PER_BLK, AA - aStart);

    __shared__ float4 sbox[MM];   // x1,y1,x2,y2
    __shared__ float4 saux[MM];   // (2/7)*area_b, (1/3)*area_b, area_b, cls bits
    __shared__ float  swgt[ANCH_PER_BLK];  // 1.0 if anchor contributes cls loss
    __shared__ float  wsum[8], wsum2[8];

    if (tid < MM) {
        float4 bx = ((const float4*)boxes)[b * MM + tid];
        float sb = (bx.z - bx.x) * (bx.w - bx.y);
        sbox[tid] = bx;
        float4 au;
        au.x = sb * (2.0f / 7.0f);
        au.y = sb * (1.0f / 3.0f);
        au.z = sb;
        au.w = __int_as_float(cls[b * MM + tid]);
        saux[tid] = au;
    }
    __syncthreads();

    float s = 0.0f;      // classification partial (units of p^2*log2(...))
    float rsum = 0.0f;   // regression partial

    // ---------- phase 1: per-anchor assignment ----------
    if (a < AA) {
        float4 an = ((const float4*)anchors)[a];
        const float ax1 = an.x, ay1 = an.y, ax2 = an.z, ay2 = an.w;
        const float aw = ax2 - ax1, ah = ay2 - ay1;
        const float sa = aw * ah;

        // division-free screen: iou >= t  <=>  inter >= t/(1+t)*(sa+sb)
        // padded boxes (-1): inter=0, sb=0 -> candidate value 0, provably
        // below both (positive) thresholds and never the argmax when pos.
        float m4 = -1e30f, m5 = -1e30f;
        #pragma unroll 2
        for (int j = 0; j < MM; ++j) {
            float4 bx = sbox[j];
            float4 au = saux[j];
            float iw = fmaxf(fminf(ax2, bx.z) - fmaxf(ax1, bx.x), 0.0f);
            float ih = fmaxf(fminf(ay2, bx.w) - fmaxf(ay1, bx.y), 0.0f);
            float inter = iw * ih;
            m4 = fmaxf(m4, inter - au.x);
            m5 = fmaxf(m5, inter - au.y);
        }
        const bool pos = (m5 >= sa * (1.0f / 3.0f));
        const bool neg = (m4 <  sa * (2.0f / 7.0f));
        swgt[tid] = (pos || neg) ? 1.0f : 0.0f;

        if (pos) {
            // argmax via cross-multiplication (division-free)
            float bi = -1.0f, bu = 1.0f;
            int bj = 0;
            for (int j = 0; j < MM; ++j) {
                float4 bx = sbox[j];
                float iw = fmaxf(fminf(ax2, bx.z) - fmaxf(ax1, bx.x), 0.0f);
                float ih = fmaxf(fminf(ay2, bx.w) - fmaxf(ay1, bx.y), 0.0f);
                float inter = iw * ih;
                float ua = fmaxf(sa + saux[j].z - inter, 1e-8f);
                if (inter * bu > bi * ua) { bi = inter; bu = ua; bj = j; }
            }

            // focal correction on the positive class
            int c = __float_as_int(saux[bj].w) - 1;
            float praw = __ldg(logits + ((size_t)b * AA + a) * KK + c);
            float p = fminf(fmaxf(praw, 1e-4f), 1.0f - 1e-4f);
            float q = 1.0f - p;
            s += (1.0f / 3.0f) * q * q * __log2f(p) - p * p * __log2f(q);

            // regression smooth-L1
            float4 gb = sbox[bj];
            float acx = ax1 + 0.5f * aw;
            float acy = ay1 + 0.5f * ah;
            float gw0 = gb.z - gb.x, gh0 = gb.w - gb.y;
            float gcx = gb.x + 0.5f * gw0;
            float gcy = gb.y + 0.5f * gh0;
            float gw = fmaxf(gw0, 1.0f), gh = fmaxf(gh0, 1.0f);
            float4 rp = ((const float4*)regp)[b * AA + a];
            float t0 = ((gcx - acx) / aw) * 10.0f;
            float t1 = ((gcy - acy) / ah) * 10.0f;
            float t2 = logf(gw / aw) * 5.0f;
            float t3 = logf(gh / ah) * 5.0f;
            rsum = smooth_l1(t0 - rp.x) + smooth_l1(t1 - rp.y)
                 + smooth_l1(t2 - rp.z) + smooth_l1(t3 - rp.w);
        }

        // per-warp positive count -> one atomic per warp
        unsigned int bal = __ballot_sync(0xffffffffu, pos);
        if ((tid & 31) == 0 && bal) atomicAdd(&g_numpos[b], __popc(bal));
    } else {
        swgt[tid] = 0.0f;
        __ballot_sync(0xffffffffu, false);
    }
    __syncthreads();

    // ---------- phase 2: coalesced focal sweep over the block's tile ----------
    {
        const float4* tile4 = (const float4*)(logits + ((size_t)b * AA + aStart) * KK);
        const int n4 = aCnt * (KK / 4);   // float4s in tile (<= 5120)
        for (int i = tid; i < n4; i += TPB) {
            float w = swgt[i / (KK / 4)];
            float4 p4 = tile4[i];
            float p0 = fminf(fmaxf(p4.x, 1e-4f), 1.0f - 1e-4f);
            float p1 = fminf(fmaxf(p4.y, 1e-4f), 1.0f - 1e-4f);
            float p2 = fminf(fmaxf(p4.z, 1e-4f), 1.0f - 1e-4f);
            float p3 = fminf(fmaxf(p4.w, 1e-4f), 1.0f - 1e-4f);
            float t = p0 * p0 * __log2f(1.0f - p0)
                    + p1 * p1 * __log2f(1.0f - p1)
                    + p2 * p2 * __log2f(1.0f - p2)
                    + p3 * p3 * __log2f(1.0f - p3);
            s += w * t;
        }
    }

    // ---------- phase 3: block reduction, one atomic each ----------
    #pragma unroll
    for (int o = 16; o > 0; o >>= 1) {
        s    += __shfl_down_sync(0xffffffffu, s, o);
        rsum += __shfl_down_sync(0xffffffffu, rsum, o);
    }
    int lane = tid & 31, wid = tid >> 5;
    if (lane == 0) { wsum[wid] = s; wsum2[wid] = rsum; }
    __syncthreads();

    if (tid == 0) {
        float t = 0.0f, t2 = 0.0f;
        #pragma unroll
        for (int i = 0; i < 8; ++i) { t += wsum[i]; t2 += wsum2[i]; }
        if (t != 0.0f)  atomicAdd(&g_cls_raw[b], t);
        if (t2 != 0.0f) atomicAdd(&g_reg_raw[b], t2);

        // ---------- phase 4: last block finalizes + resets ----------
        __threadfence();
        unsigned int prev = atomicAdd(&g_done, 1u);
        if (prev == NBLKS - 1) {
            float cm = 0.0f, rm = 0.0f;
            #pragma unroll
            for (int bb = 0; bb < BB; ++bb) {
                float np = fmaxf((float)g_numpos[bb], 1.0f);
                cm += (-0.75f * 0.69314718055994531f) * g_cls_raw[bb] / np;
                rm += g_reg_raw[bb] / (4.0f * np);
                g_cls_raw[bb] = 0.0f;
                g_reg_raw[bb] = 0.0f;
                g_numpos[bb] = 0;
            }
            cm *= (1.0f / (float)BB);
            rm *= (1.0f / (float)BB);
            out[0] = cm;
            out[1] = rm;
            out[2] = cm + rm;
            g_done = 0u;
        }
    }
}

extern "C" void kernel_launch(void* const* d_in, const int* in_sizes, int n_in,
                              void* d_out, int out_size) {
    const float* logits  = (const float*)d_in[0];
    const float* regp    = (const float*)d_in[1];
    const float* anchors = (const float*)d_in[2];
    const float* boxes   = (const float*)d_in[3];
    const int*   cls     = (const int*)d_in[4];
    float* out = (float*)d_out;

    dim3 grid(NBLKX, BB);
    retina_fused_kernel<<<grid, TPB>>>(logits, regp, anchors, boxes, cls, out);
}